// round 4
// baseline (speedup 1.0000x reference)
#include <cuda_runtime.h>
#include <cuda_bf16.h>
#include <math.h>

#define B 32
#define P 32768
#define O 32
#define NCH 16          // chunks per batch in match kernel (P / 2048)
#define PPB 2048        // priors per block (256 threads * 8)
#define THRESH 0.35f
#define LBLK 128                // loss blocks per batch
#define NPART (LBLK * B)        // 4096 partial slots

// ---------------- scratch (static device globals; no allocation) ----------------
__device__ float2   g_bt  [B * P];        // (iou, idx-as-float) per (b,p)
__device__ float    g_mine[B * P];        // pos ? 0 : ce
__device__ unsigned g_bp_k[B * O * NCH];  // packed best-prior key per (b,o,chunk)
__device__ int      g_bp_p[B * O * NCH];
__device__ int      g_num_pos[B];
__device__ float    g_part_l[NPART];
__device__ float    g_part_c[NPART];
__device__ double   g_neg_b[B];
__device__ int      g_done;

// ---------------- K1: match (IoU argmaxes, packed-int compare) ----------------
// grid (NCH, B), block 256. Each thread handles 8 priors (stride 256).
__global__ void __launch_bounds__(256) match_kernel(const float* __restrict__ priors,
                                                    const float* __restrict__ targets) {
    const int b     = blockIdx.y;
    const int chunk = blockIdx.x;
    const int tid   = threadIdx.x;
    const int lane  = tid & 31;
    const int wid   = tid >> 5;

    __shared__ float    s_tx0[O], s_ty0[O], s_tx1[O], s_ty1[O], s_ta[O];
    __shared__ unsigned s_wk[O][8];
    __shared__ int      s_wp[O][8];

    // fold init: one block zeroes cross-kernel accumulators
    if (b == 0 && chunk == 0) {
        if (tid < B) g_num_pos[tid] = 0;
        if (tid == 0) g_done = 0;
    }

    if (tid < O) {
        const float* t = targets + (size_t)(b * O + tid) * 5;
        float x0 = t[0], y0 = t[1], x1 = t[2], y1 = t[3];
        s_tx0[tid] = x0; s_ty0[tid] = y0; s_tx1[tid] = x1; s_ty1[tid] = y1;
        s_ta[tid] = __fmul_rn(__fsub_rn(x1, x0), __fsub_rn(y1, y0));
    }
    __syncthreads();

    const int p0 = chunk * PPB + tid;

    float px0[8], py0[8], px1[8], py1[8], pa[8];
#pragma unroll
    for (int i = 0; i < 8; ++i) {
        float4 pr = reinterpret_cast<const float4*>(priors)[p0 + i * 256];
        float hw = __fmul_rn(pr.z, 0.5f);
        float hh = __fmul_rn(pr.w, 0.5f);
        px0[i] = __fsub_rn(pr.x, hw);
        py0[i] = __fsub_rn(pr.y, hh);
        px1[i] = __fadd_rn(pr.x, hw);
        py1[i] = __fadd_rn(pr.y, hh);
        pa[i]  = __fmul_rn(__fsub_rn(px1[i], px0[i]), __fsub_rn(py1[i], py0[i]));
    }

    // packed best-truth key per prior: (q_bits & ~31) | (31-o). init = q=0,o=0.
    unsigned bk[8];
#pragma unroll
    for (int i = 0; i < 8; ++i) bk[i] = 31u;

    for (int o = 0; o < O; ++o) {
        const float tx0 = s_tx0[o], ty0 = s_ty0[o], tx1 = s_tx1[o], ty1 = s_ty1[o], ta = s_ta[o];
        const unsigned oc = 31u - (unsigned)o;
        unsigned ck = 7u;   // (q=0, i=0) per-thread best over p for this o
#pragma unroll
        for (int i = 0; i < 8; ++i) {
            float wx = fmaxf(fminf(px1[i], tx1) - fmaxf(px0[i], tx0), 0.0f);
            float wy = fmaxf(fminf(py1[i], ty1) - fmaxf(py0[i], ty0), 0.0f);
            float in_ = wx * wy;
            float un  = (pa[i] + ta) - in_;          // > 0 always
            float q   = __fdividef(in_, un);         // >= 0
            unsigned qb = __float_as_uint(q);
            unsigned ub = (qb & 0xFFFFFFE0u) | oc;   // LOP3
            bk[i] = umax(bk[i], ub);                 // first-o wins on equal q
            unsigned uc = (qb & 0xFFFFFFF8u) | (7u - (unsigned)i);
            ck = umax(ck, uc);                       // lowest-i wins on equal q
        }
        int cp = p0 + (7 - (int)(ck & 7u)) * 256;
        // warp argmax over 256 priors; equal ck => keep lower lane (= lower p)
#pragma unroll
        for (int d = 16; d > 0; d >>= 1) {
            unsigned ok = __shfl_down_sync(0xffffffffu, ck, d);
            int      op = __shfl_down_sync(0xffffffffu, cp, d);
            if (ok > ck) { ck = ok; cp = op; }
        }
        if (lane == 0) { s_wk[o][wid] = ck; s_wp[o][wid] = cp; }
    }

    // per-prior output: recompute winner's IoU with exact IEEE ops (matches reference)
#pragma unroll
    for (int i = 0; i < 8; ++i) {
        int o = 31 - (int)(bk[i] & 31u);
        float tx0 = s_tx0[o], ty0 = s_ty0[o], tx1 = s_tx1[o], ty1 = s_ty1[o], ta = s_ta[o];
        float wx = fmaxf(__fsub_rn(fminf(px1[i], tx1), fmaxf(px0[i], tx0)), 0.0f);
        float wy = fmaxf(__fsub_rn(fminf(py1[i], ty1), fmaxf(py0[i], ty0)), 0.0f);
        float in_ = __fmul_rn(wx, wy);
        float un  = __fsub_rn(__fadd_rn(pa[i], ta), in_);
        g_bt[b * P + p0 + i * 256] = make_float2(__fdiv_rn(in_, un), __int_as_float(o));
    }

    __syncthreads();
    if (tid < O) {
        int o = tid;
        unsigned ck = s_wk[o][0]; int cp = s_wp[o][0];
#pragma unroll
        for (int w = 1; w < 8; ++w) {
            unsigned ok = s_wk[o][w]; int op = s_wp[o][w];
            if (ok > ck || (ok == ck && op < cp)) { ck = ok; cp = op; }
        }
        int idx = (b * O + o) * NCH + chunk;
        g_bp_k[idx] = ck; g_bp_p[idx] = cp;
    }
}

// ---------------- K2: reduce best-prior per (b,o) + forced-match fix ----------------
__global__ void fix_kernel() {
    const int b = blockIdx.x;
    const int o = threadIdx.x;
    __shared__ int s_bpi[O];

    int base = (b * O + o) * NCH;
    unsigned ck = g_bp_k[base]; int cp = g_bp_p[base];
#pragma unroll
    for (int c = 1; c < NCH; ++c) {
        unsigned ok = g_bp_k[base + c]; int op = g_bp_p[base + c];
        if (ok > ck || (ok == ck && op < cp)) { ck = ok; cp = op; }
    }
    s_bpi[o] = cp;
    __syncthreads();
    if (o == 0) {
        // sequential, ascending o: last-wins on duplicate indices (XLA scatter order)
        for (int j = 0; j < O; ++j) {
            int p = s_bpi[j];
            g_bt[b * P + p] = make_float2(2.0f, __int_as_float(j));
        }
    }
}

// ---------------- K3: per-prior losses (atomic-free block partials) ----------------
__device__ __forceinline__ float smooth_l1(float d) {
    float ad = fabsf(d);
    return (ad < 1.0f) ? __fmul_rn(__fmul_rn(0.5f, d), d) : __fsub_rn(ad, 0.5f);
}

__global__ void __launch_bounds__(256) loss_kernel(const float* __restrict__ loc,
                                                   const float* __restrict__ conf,
                                                   const float* __restrict__ priors,
                                                   const float* __restrict__ targets) {
    const int b = blockIdx.y;
    const int p = blockIdx.x * 256 + threadIdx.x;
    const int lane = threadIdx.x & 31;
    const int wid  = threadIdx.x >> 5;

    __shared__ float s_t[O][4];
    __shared__ float s_lab[O];
    __shared__ float s_ll[8], s_pce[8];
    __shared__ int   s_np[8];
    if (threadIdx.x < O) {
        const float* t = targets + (size_t)(b * O + threadIdx.x) * 5;
        s_t[threadIdx.x][0] = t[0]; s_t[threadIdx.x][1] = t[1];
        s_t[threadIdx.x][2] = t[2]; s_t[threadIdx.x][3] = t[3];
        s_lab[threadIdx.x]  = t[4];
    }
    __syncthreads();

    const int bp = b * P + p;
    float2 bt = g_bt[bp];
    const int o = __float_as_int(bt.y);
    const int ct = (bt.x < THRESH) ? 0 : ((int)s_lab[o] + 1);
    const bool pos = (ct > 0);

    float2 cd = reinterpret_cast<const float2*>(conf)[bp];
    float m  = fmaxf(cd.x, cd.y);
    float mn = fminf(cd.x, cd.y);
    float lse = __fadd_rn(m, __logf(__fadd_rn(1.0f, __expf(__fsub_rn(mn, m)))));
    float picked = (ct == 0) ? cd.x : cd.y;
    float ce = __fsub_rn(lse, picked);

    g_mine[bp] = pos ? 0.0f : ce;

    unsigned bal = __ballot_sync(0xffffffffu, pos);
    float ll = 0.0f, pce = 0.0f;
    if (bal) {   // warp-uniform skip
        if (pos) {
            float4 pr = reinterpret_cast<const float4*>(priors)[p];
            float mx0 = s_t[o][0], my0 = s_t[o][1], mx1 = s_t[o][2], my1 = s_t[o][3];
            float lt0 = __fdividef(__fsub_rn(__fmul_rn(__fadd_rn(mx0, mx1), 0.5f), pr.x),
                                   __fmul_rn(0.1f, pr.z));
            float lt1 = __fdividef(__fsub_rn(__fmul_rn(__fadd_rn(my0, my1), 0.5f), pr.y),
                                   __fmul_rn(0.1f, pr.w));
            float lt2 = __fmul_rn(__logf(__fdividef(__fsub_rn(mx1, mx0), pr.z)), 5.0f);
            float lt3 = __fmul_rn(__logf(__fdividef(__fsub_rn(my1, my0), pr.w)), 5.0f);
            float4 ld = reinterpret_cast<const float4*>(loc)[bp];
            ll = __fadd_rn(__fadd_rn(smooth_l1(__fsub_rn(ld.x, lt0)),
                                     smooth_l1(__fsub_rn(ld.y, lt1))),
                           __fadd_rn(smooth_l1(__fsub_rn(ld.z, lt2)),
                                     smooth_l1(__fsub_rn(ld.w, lt3))));
            pce = ce;
        }
#pragma unroll
        for (int d = 16; d > 0; d >>= 1) {
            ll  += __shfl_down_sync(0xffffffffu, ll, d);
            pce += __shfl_down_sync(0xffffffffu, pce, d);
        }
    }
    if (lane == 0) { s_ll[wid] = ll; s_pce[wid] = pce; s_np[wid] = __popc(bal); }
    __syncthreads();
    if (threadIdx.x == 0) {
        float tl = 0.0f, tc = 0.0f; int tn = 0;
#pragma unroll
        for (int w = 0; w < 8; ++w) { tl += s_ll[w]; tc += s_pce[w]; tn += s_np[w]; }
        int slot = b * LBLK + blockIdx.x;
        g_part_l[slot] = tl;
        g_part_c[slot] = tc;
        if (tn) atomicAdd(&g_num_pos[b], tn);
    }
}

// ---------------- K4: per-batch top-k sum (radix select, warp-aggregated hist) ----------------
__device__ __forceinline__ void hist_add(unsigned u, unsigned himask, unsigned prefix,
                                         int shift, unsigned* s_hist, int lane) {
    bool act = (u & himask) == prefix;
    unsigned bin = act ? ((u >> shift) & 255u) : 0xFFFFFFFFu;
    unsigned mm = __match_any_sync(0xffffffffu, bin);
    if (act && ((__ffs(mm) - 1) == lane))
        atomicAdd(&s_hist[bin], (unsigned)__popc(mm));
}

__global__ void __launch_bounds__(1024) select_kernel(float* __restrict__ out) {
    const int b = blockIdx.x;
    const int tid = threadIdx.x;
    const int lane = tid & 31;
    const int wid  = tid >> 5;

    __shared__ unsigned s_hist[256];
    __shared__ unsigned s_wsum[8];
    __shared__ unsigned s_selb;
    __shared__ unsigned s_kk2;
    __shared__ double   s_part[32];
    __shared__ int      s_ticket;

    int np = g_num_pos[b];
    long long kll = (long long)7 * np;
    int k = (kll < (P - 1)) ? (int)kll : (P - 1);

    double myneg = 0.0;
    if (k > 0) {
        const float4* mine4 = reinterpret_cast<const float4*>(g_mine + (size_t)b * P);
        unsigned prefix = 0;
        unsigned kk = (unsigned)k;

        for (int pass = 0; pass < 4; ++pass) {
            const int shift = 24 - 8 * pass;
            if (tid < 256) s_hist[tid] = 0;
            __syncthreads();
            unsigned himask = (pass == 0) ? 0u : (0xFFFFFFFFu << (shift + 8));
#pragma unroll
            for (int it = 0; it < 8; ++it) {
                float4 x = mine4[tid + it * 1024];
                hist_add(__float_as_uint(x.x), himask, prefix, shift, s_hist, lane);
                hist_add(__float_as_uint(x.y), himask, prefix, shift, s_hist, lane);
                hist_add(__float_as_uint(x.z), himask, prefix, shift, s_hist, lane);
                hist_add(__float_as_uint(x.w), himask, prefix, shift, s_hist, lane);
            }
            __syncthreads();
            unsigned v = (tid < 256) ? s_hist[255 - tid] : 0u;
            unsigned c = v;
#pragma unroll
            for (int d = 1; d < 32; d <<= 1) {
                unsigned x = __shfl_up_sync(0xffffffffu, c, d);
                if (lane >= d) c += x;
            }
            if (tid < 256 && lane == 31) s_wsum[wid] = c;
            __syncthreads();
            if (tid < 256) {
                unsigned off = 0;
#pragma unroll
                for (int j = 0; j < 8; ++j) if (j < wid) off += s_wsum[j];
                c += off;
                if (c >= kk && (c - v) < kk) {
                    s_selb = (unsigned)(255 - tid);
                    s_kk2  = kk - (c - v);
                }
            }
            __syncthreads();
            prefix |= (s_selb << shift);
            kk = s_kk2;
            __syncthreads();
        }

        float T = __uint_as_float(prefix);
        float sum = 0.0f;
#pragma unroll
        for (int it = 0; it < 8; ++it) {
            float4 x = mine4[tid + it * 1024];
            if (__float_as_uint(x.x) > prefix) sum = __fadd_rn(sum, x.x);
            if (__float_as_uint(x.y) > prefix) sum = __fadd_rn(sum, x.y);
            if (__float_as_uint(x.z) > prefix) sum = __fadd_rn(sum, x.z);
            if (__float_as_uint(x.w) > prefix) sum = __fadd_rn(sum, x.w);
        }
#pragma unroll
        for (int d = 16; d > 0; d >>= 1) sum += __shfl_down_sync(0xffffffffu, sum, d);
        if (lane == 0) s_part[wid] = (double)sum;
        __syncthreads();
        if (tid == 0) {
            double tot = 0.0;
#pragma unroll
            for (int j = 0; j < 32; ++j) tot += s_part[j];
            myneg = tot + (double)kk * (double)T;
        }
    }

    // publish per-batch result, take ticket; last block finalizes
    if (tid == 0) {
        g_neg_b[b] = myneg;
        __threadfence();
        s_ticket = atomicAdd(&g_done, 1);
    }
    __syncthreads();
    if (s_ticket != B - 1) return;

    double l = 0.0, c = 0.0;
#pragma unroll
    for (int it = 0; it < NPART / 1024; ++it) {
        l += (double)g_part_l[tid + it * 1024];
        c += (double)g_part_c[tid + it * 1024];
    }
#pragma unroll
    for (int d = 16; d > 0; d >>= 1) {
        l += __shfl_down_sync(0xffffffffu, l, d);
        c += __shfl_down_sync(0xffffffffu, c, d);
    }
    __shared__ double s_l2[32], s_c2[32];
    if (lane == 0) { s_l2[wid] = l; s_c2[wid] = c; }
    __syncthreads();
    if (tid == 0) {
        double tl = 0.0, tc = 0.0;
#pragma unroll
        for (int j = 0; j < 32; ++j) { tl += s_l2[j]; tc += s_c2[j]; }
        double tneg = 0.0;
        int s = 0;
#pragma unroll
        for (int j = 0; j < B; ++j) {
            tneg += __ldcg(&g_neg_b[j]);
            s += g_num_pos[j];
        }
        double N = (double)s;
        if (N < 1.0) N = 1.0;
        out[0] = (float)(tl / N);
        out[1] = (float)((tc + tneg) / N);
    }
}

// ---------------- launch ----------------
extern "C" void kernel_launch(void* const* d_in, const int* in_sizes, int n_in,
                              void* d_out, int out_size) {
    const float* loc     = (const float*)d_in[0];
    const float* conf    = (const float*)d_in[1];
    const float* priors  = (const float*)d_in[2];
    const float* targets = (const float*)d_in[3];
    float* out = (float*)d_out;

    match_kernel<<<dim3(NCH, B), 256>>>(priors, targets);
    fix_kernel<<<B, O>>>();
    loss_kernel<<<dim3(LBLK, B), 256>>>(loc, conf, priors, targets);
    select_kernel<<<B, 1024>>>(out);
}

// round 5
// speedup vs baseline: 1.1739x; 1.1739x over previous
#include <cuda_runtime.h>
#include <cuda_bf16.h>
#include <math.h>

#define B 32
#define P 32768
#define O 32
#define NCH 16          // chunks per batch in match kernel (P / 2048)
#define PPB 2048        // priors per block (256 threads * 8)
#define THRESH 0.35f
#define LBLK 128                // loss blocks per batch
#define NPART (LBLK * B)        // 4096 partial slots
#define NSB 8                   // select blocks per batch
#define SLICE (P / NSB)         // 4096 elements per select block

// ---------------- scratch (static device globals; no allocation) ----------------
__device__ float2   g_bt  [B * P];        // (iou, idx-as-float) per (b,p)
__device__ float    g_mine[B * P];        // pos ? 0 : ce
__device__ unsigned g_bp_k[B * O * NCH];  // packed best-prior key per (b,o,chunk)
__device__ int      g_bp_p[B * O * NCH];
__device__ int      g_num_pos[B];
__device__ float    g_part_l[NPART];
__device__ float    g_part_c[NPART];
__device__ unsigned g_hist[B * 4 * 256];  // per-batch per-pass global histograms
__device__ unsigned g_sel [B * 4];        // published (bin<<24)|kk per pass
__device__ unsigned g_cnt [B * 5];        // arrival counters (4 passes + sum)
__device__ double   g_psum[B * NSB];      // per-slice selected sums
__device__ double   g_neg_b[B];
__device__ int      g_done;

// ---------------- K1: match (IoU argmaxes, packed-int compare) ----------------
// grid (NCH, B), block 256. Each thread handles 8 priors (stride 256).
__global__ void __launch_bounds__(256) match_kernel(const float* __restrict__ priors,
                                                    const float* __restrict__ targets) {
    const int b     = blockIdx.y;
    const int chunk = blockIdx.x;
    const int tid   = threadIdx.x;
    const int lane  = tid & 31;
    const int wid   = tid >> 5;

    __shared__ float    s_tx0[O], s_ty0[O], s_tx1[O], s_ty1[O], s_ta[O];
    __shared__ unsigned s_wk[O][8];
    __shared__ int      s_wp[O][8];

    // fold init: one block zeroes the positive counters
    if (b == 0 && chunk == 0) {
        if (tid < B) g_num_pos[tid] = 0;
    }

    if (tid < O) {
        const float* t = targets + (size_t)(b * O + tid) * 5;
        float x0 = t[0], y0 = t[1], x1 = t[2], y1 = t[3];
        s_tx0[tid] = x0; s_ty0[tid] = y0; s_tx1[tid] = x1; s_ty1[tid] = y1;
        s_ta[tid] = __fmul_rn(__fsub_rn(x1, x0), __fsub_rn(y1, y0));
    }
    __syncthreads();

    const int p0 = chunk * PPB + tid;

    float px0[8], py0[8], px1[8], py1[8], pa[8];
#pragma unroll
    for (int i = 0; i < 8; ++i) {
        float4 pr = reinterpret_cast<const float4*>(priors)[p0 + i * 256];
        float hw = __fmul_rn(pr.z, 0.5f);
        float hh = __fmul_rn(pr.w, 0.5f);
        px0[i] = __fsub_rn(pr.x, hw);
        py0[i] = __fsub_rn(pr.y, hh);
        px1[i] = __fadd_rn(pr.x, hw);
        py1[i] = __fadd_rn(pr.y, hh);
        pa[i]  = __fmul_rn(__fsub_rn(px1[i], px0[i]), __fsub_rn(py1[i], py0[i]));
    }

    // packed best-truth key per prior: (q_bits & ~31) | (31-o). init = q=0,o=0.
    unsigned bk[8];
#pragma unroll
    for (int i = 0; i < 8; ++i) bk[i] = 31u;

    for (int o = 0; o < O; ++o) {
        const float tx0 = s_tx0[o], ty0 = s_ty0[o], tx1 = s_tx1[o], ty1 = s_ty1[o], ta = s_ta[o];
        const unsigned oc = 31u - (unsigned)o;
        unsigned ck = 7u;   // (q=0, slot=0) per-thread best over own 8 priors for this o
#pragma unroll
        for (int i = 0; i < 8; ++i) {
            float wx = fmaxf(fminf(px1[i], tx1) - fmaxf(px0[i], tx0), 0.0f);
            float wy = fmaxf(fminf(py1[i], ty1) - fmaxf(py0[i], ty0), 0.0f);
            float in_ = wx * wy;
            float un  = (pa[i] + ta) - in_;          // > 0 always
            float q   = __fdividef(in_, un);         // >= 0
            unsigned qb = __float_as_uint(q);
            bk[i] = umax(bk[i], (qb & 0xFFFFFFE0u) | oc);            // first-o wins on tie
            ck    = umax(ck,    (qb & 0xFFFFFFF8u) | (7u - (unsigned)i)); // lowest slot wins
        }
        // single-instruction warp argmax; tie -> lowest lane (= lowest p)
        unsigned mx = __reduce_max_sync(0xffffffffu, ck);
        unsigned bal = __ballot_sync(0xffffffffu, ck == mx);
        if (lane == 0) {
            int src = __ffs(bal) - 1;
            s_wk[o][wid] = mx;
            s_wp[o][wid] = chunk * PPB + wid * 32 + src + (7 - (int)(mx & 7u)) * 256;
        }
    }

    // per-prior output: recompute winner's IoU with exact IEEE ops (matches reference)
#pragma unroll
    for (int i = 0; i < 8; ++i) {
        int o = 31 - (int)(bk[i] & 31u);
        float tx0 = s_tx0[o], ty0 = s_ty0[o], tx1 = s_tx1[o], ty1 = s_ty1[o], ta = s_ta[o];
        float wx = fmaxf(__fsub_rn(fminf(px1[i], tx1), fmaxf(px0[i], tx0)), 0.0f);
        float wy = fmaxf(__fsub_rn(fminf(py1[i], ty1), fmaxf(py0[i], ty0)), 0.0f);
        float in_ = __fmul_rn(wx, wy);
        float un  = __fsub_rn(__fadd_rn(pa[i], ta), in_);
        g_bt[b * P + p0 + i * 256] = make_float2(__fdiv_rn(in_, un), __int_as_float(o));
    }

    __syncthreads();
    if (tid < O) {
        int o = tid;
        unsigned ck = s_wk[o][0]; int cp = s_wp[o][0];
#pragma unroll
        for (int w = 1; w < 8; ++w) {
            unsigned ok = s_wk[o][w]; int op = s_wp[o][w];
            if (ok > ck || (ok == ck && op < cp)) { ck = ok; cp = op; }
        }
        int idx = (b * O + o) * NCH + chunk;
        g_bp_k[idx] = ck; g_bp_p[idx] = cp;
    }
}

// ---------------- K2: reduce best-prior + forced-match fix + zero select state ----------------
__global__ void __launch_bounds__(256) fix_kernel() {
    const int b = blockIdx.x;
    const int t = threadIdx.x;
    __shared__ int s_bpi[O];

    // zero per-batch select coordination state (graph-replay safe)
#pragma unroll
    for (int i = t; i < 4 * 256; i += 256) g_hist[b * 1024 + i] = 0;
    if (t < 4) g_sel[b * 4 + t] = 0;
    if (t < 5) g_cnt[b * 5 + t] = 0;
    if (b == 0 && t == 0) g_done = 0;

    if (t < O) {
        int base = (b * O + t) * NCH;
        unsigned ck = g_bp_k[base]; int cp = g_bp_p[base];
#pragma unroll
        for (int c = 1; c < NCH; ++c) {
            unsigned ok = g_bp_k[base + c]; int op = g_bp_p[base + c];
            if (ok > ck || (ok == ck && op < cp)) { ck = ok; cp = op; }
        }
        s_bpi[t] = cp;
    }
    __syncthreads();
    if (t == 0) {
        // sequential, ascending o: last-wins on duplicate indices (XLA scatter order)
        for (int j = 0; j < O; ++j) {
            int p = s_bpi[j];
            g_bt[b * P + p] = make_float2(2.0f, __int_as_float(j));
        }
    }
}

// ---------------- K3: per-prior losses (atomic-free block partials) ----------------
__device__ __forceinline__ float smooth_l1(float d) {
    float ad = fabsf(d);
    return (ad < 1.0f) ? __fmul_rn(__fmul_rn(0.5f, d), d) : __fsub_rn(ad, 0.5f);
}

__global__ void __launch_bounds__(256) loss_kernel(const float* __restrict__ loc,
                                                   const float* __restrict__ conf,
                                                   const float* __restrict__ priors,
                                                   const float* __restrict__ targets) {
    const int b = blockIdx.y;
    const int p = blockIdx.x * 256 + threadIdx.x;
    const int lane = threadIdx.x & 31;
    const int wid  = threadIdx.x >> 5;

    __shared__ float s_t[O][4];
    __shared__ float s_lab[O];
    __shared__ float s_ll[8], s_pce[8];
    __shared__ int   s_np[8];
    if (threadIdx.x < O) {
        const float* t = targets + (size_t)(b * O + threadIdx.x) * 5;
        s_t[threadIdx.x][0] = t[0]; s_t[threadIdx.x][1] = t[1];
        s_t[threadIdx.x][2] = t[2]; s_t[threadIdx.x][3] = t[3];
        s_lab[threadIdx.x]  = t[4];
    }
    __syncthreads();

    const int bp = b * P + p;
    float2 bt = g_bt[bp];
    const int o = __float_as_int(bt.y);
    const int ct = (bt.x < THRESH) ? 0 : ((int)s_lab[o] + 1);
    const bool pos = (ct > 0);

    float2 cd = reinterpret_cast<const float2*>(conf)[bp];
    float m  = fmaxf(cd.x, cd.y);
    float mn = fminf(cd.x, cd.y);
    float lse = __fadd_rn(m, __logf(__fadd_rn(1.0f, __expf(__fsub_rn(mn, m)))));
    float picked = (ct == 0) ? cd.x : cd.y;
    float ce = __fsub_rn(lse, picked);

    g_mine[bp] = pos ? 0.0f : ce;

    unsigned bal = __ballot_sync(0xffffffffu, pos);
    float ll = 0.0f, pce = 0.0f;
    if (bal) {   // warp-uniform skip
        if (pos) {
            float4 pr = reinterpret_cast<const float4*>(priors)[p];
            float mx0 = s_t[o][0], my0 = s_t[o][1], mx1 = s_t[o][2], my1 = s_t[o][3];
            float lt0 = __fdividef(__fsub_rn(__fmul_rn(__fadd_rn(mx0, mx1), 0.5f), pr.x),
                                   __fmul_rn(0.1f, pr.z));
            float lt1 = __fdividef(__fsub_rn(__fmul_rn(__fadd_rn(my0, my1), 0.5f), pr.y),
                                   __fmul_rn(0.1f, pr.w));
            float lt2 = __fmul_rn(__logf(__fdividef(__fsub_rn(mx1, mx0), pr.z)), 5.0f);
            float lt3 = __fmul_rn(__logf(__fdividef(__fsub_rn(my1, my0), pr.w)), 5.0f);
            float4 ld = reinterpret_cast<const float4*>(loc)[bp];
            ll = __fadd_rn(__fadd_rn(smooth_l1(__fsub_rn(ld.x, lt0)),
                                     smooth_l1(__fsub_rn(ld.y, lt1))),
                           __fadd_rn(smooth_l1(__fsub_rn(ld.z, lt2)),
                                     smooth_l1(__fsub_rn(ld.w, lt3))));
            pce = ce;
        }
#pragma unroll
        for (int d = 16; d > 0; d >>= 1) {
            ll  += __shfl_down_sync(0xffffffffu, ll, d);
            pce += __shfl_down_sync(0xffffffffu, pce, d);
        }
    }
    if (lane == 0) { s_ll[wid] = ll; s_pce[wid] = pce; s_np[wid] = __popc(bal); }
    __syncthreads();
    if (threadIdx.x == 0) {
        float tl = 0.0f, tc = 0.0f; int tn = 0;
#pragma unroll
        for (int w = 0; w < 8; ++w) { tl += s_ll[w]; tc += s_pce[w]; tn += s_np[w]; }
        int slot = b * LBLK + blockIdx.x;
        g_part_l[slot] = tl;
        g_part_c[slot] = tc;
        if (tn) atomicAdd(&g_num_pos[b], tn);
    }
}

// ---------------- K4: distributed radix top-k sum + fused finalize ----------------
// grid (NSB, B), 256 threads. Data loaded once into registers; 8 blocks per batch
// cooperate via global hist + spin-published selection word (all blocks co-resident).
__global__ void __launch_bounds__(256) select_kernel(float* __restrict__ out) {
    const int sb  = blockIdx.x;
    const int b   = blockIdx.y;
    const int tid = threadIdx.x;
    const int lane = tid & 31;
    const int wid  = tid >> 5;

    __shared__ unsigned s_hist[256];
    __shared__ unsigned s_wsum[8];
    __shared__ unsigned s_word;
    __shared__ int      s_last;
    __shared__ int      s_fin;
    __shared__ double   s_part[8];
    __shared__ double   s_l2[8], s_c2[8];

    int np = g_num_pos[b];
    long long kll = (long long)7 * np;
    int k = (kll < (P - 1)) ? (int)kll : (P - 1);

    // load slice once into registers
    unsigned data[16];
    const uint4* src = reinterpret_cast<const uint4*>(g_mine + (size_t)b * P + sb * SLICE);
#pragma unroll
    for (int v = 0; v < 4; ++v) {
        uint4 x = src[tid * 4 + v];
        data[v * 4 + 0] = x.x; data[v * 4 + 1] = x.y;
        data[v * 4 + 2] = x.z; data[v * 4 + 3] = x.w;
    }

    unsigned prefix = 0;
    unsigned kk = (unsigned)(k > 0 ? k : 0);

    if (k > 0) {
#pragma unroll
        for (int pass = 0; pass < 4; ++pass) {
            const int shift = 24 - 8 * pass;
            s_hist[tid] = 0;
            __syncthreads();
            unsigned himask = pass ? (0xFFFFFFFFu << (shift + 8)) : 0u;
#pragma unroll
            for (int e = 0; e < 16; ++e) {
                unsigned u = data[e];
                if ((u & himask) == prefix) atomicAdd(&s_hist[(u >> shift) & 255u], 1u);
            }
            __syncthreads();
            unsigned hv = s_hist[tid];
            if (hv) atomicAdd(&g_hist[(b * 4 + pass) * 256 + tid], hv);
            __threadfence();
            __syncthreads();
            if (tid == 0) s_last = (atomicAdd(&g_cnt[b * 5 + pass], 1u) == NSB - 1);
            __syncthreads();
            if (s_last) {
                // last-arriving block: all contributions visible; do the 256-bin scan
                unsigned v = __ldcg(&g_hist[(b * 4 + pass) * 256 + (255 - tid)]);
                unsigned c = v;
#pragma unroll
                for (int d = 1; d < 32; d <<= 1) {
                    unsigned x = __shfl_up_sync(0xffffffffu, c, d);
                    if (lane >= d) c += x;
                }
                if (lane == 31) s_wsum[wid] = c;
                __syncthreads();
                unsigned off = 0;
#pragma unroll
                for (int j = 0; j < 8; ++j) if (j < wid) off += s_wsum[j];
                c += off;
                if (c >= kk && (c - v) < kk)
                    s_word = ((unsigned)(255 - tid) << 24) | (kk - (c - v));
                __syncthreads();
                if (tid == 0) atomicExch(&g_sel[b * 4 + pass], s_word);
            } else {
                if (tid == 0) {
                    unsigned w;
                    do { w = atomicOr(&g_sel[b * 4 + pass], 0u); } while (w == 0u);
                    s_word = w;
                }
                __syncthreads();
            }
            unsigned word = s_word;
            prefix |= (word >> 24) << shift;
            kk = word & 0x00FFFFFFu;
            __syncthreads();
        }
    }

    // sum of selected elements in this slice
    float fsum = 0.0f;
    if (k > 0) {
#pragma unroll
        for (int e = 0; e < 16; ++e) {
            unsigned u = data[e];
            if (u > prefix) fsum = __fadd_rn(fsum, __uint_as_float(u));
        }
    }
#pragma unroll
    for (int d = 16; d > 0; d >>= 1) fsum += __shfl_down_sync(0xffffffffu, fsum, d);
    if (lane == 0) s_part[wid] = (double)fsum;
    __syncthreads();
    if (tid == 0) {
        double bl = 0.0;
#pragma unroll
        for (int j = 0; j < 8; ++j) bl += s_part[j];
        g_psum[b * NSB + sb] = bl;
        __threadfence();
        int fin = 0;
        if (atomicAdd(&g_cnt[b * 5 + 4], 1u) == NSB - 1) {
            // last slice of this batch: combine in fixed order (deterministic)
            double tot = 0.0;
#pragma unroll
            for (int j = 0; j < NSB; ++j) tot += __ldcg(&g_psum[b * NSB + j]);
            if (k > 0) tot += (double)kk * (double)__uint_as_float(prefix);
            g_neg_b[b] = tot;
            __threadfence();
            fin = (atomicAdd(&g_done, 1) == B - 1);
        }
        s_fin = fin;
    }
    __syncthreads();
    if (!s_fin) return;

    // global finalize (this is the last block to finish any batch)
    double l = 0.0, c = 0.0;
#pragma unroll
    for (int it = 0; it < NPART / 256; ++it) {
        l += (double)g_part_l[tid + it * 256];
        c += (double)g_part_c[tid + it * 256];
    }
#pragma unroll
    for (int d = 16; d > 0; d >>= 1) {
        l += __shfl_down_sync(0xffffffffu, l, d);
        c += __shfl_down_sync(0xffffffffu, c, d);
    }
    if (lane == 0) { s_l2[wid] = l; s_c2[wid] = c; }
    __syncthreads();
    if (tid == 0) {
        double tl = 0.0, tc = 0.0;
#pragma unroll
        for (int j = 0; j < 8; ++j) { tl += s_l2[j]; tc += s_c2[j]; }
        double tneg = 0.0;
        int s = 0;
#pragma unroll
        for (int j = 0; j < B; ++j) {
            tneg += __ldcg(&g_neg_b[j]);
            s += g_num_pos[j];
        }
        double N = (double)s;
        if (N < 1.0) N = 1.0;
        out[0] = (float)(tl / N);
        out[1] = (float)((tc + tneg) / N);
    }
}

// ---------------- launch ----------------
extern "C" void kernel_launch(void* const* d_in, const int* in_sizes, int n_in,
                              void* d_out, int out_size) {
    const float* loc     = (const float*)d_in[0];
    const float* conf    = (const float*)d_in[1];
    const float* priors  = (const float*)d_in[2];
    const float* targets = (const float*)d_in[3];
    float* out = (float*)d_out;

    match_kernel<<<dim3(NCH, B), 256>>>(priors, targets);
    fix_kernel<<<B, 256>>>();
    loss_kernel<<<dim3(LBLK, B), 256>>>(loc, conf, priors, targets);
    select_kernel<<<dim3(NSB, B), 256>>>(out);
}